// round 12
// baseline (speedup 1.0000x reference)
#include <cuda_runtime.h>
#include <cuda_bf16.h>

#define BB 64
#define SS 2048
#define RR 1024
#define HH 512
#define NOWN 8                  // scores owned per thread in softmax prologue
#define NSPLIT 16               // S-chunks in k4 (1024 blocks -> 6.9 waves)
#define SCHUNK (SS / NSPLIT)    // 128

// Scratch (allocation-free rule: __device__ globals)
__device__ float g_att_h[BB * HH];   // 128 KB
__device__ float g_score[BB * SS];   // 512 KB (raw scores; softmax fused into k4)

__device__ __forceinline__ float fast_tanh(float x) {
    float y;
    asm("tanh.approx.f32 %0, %1;" : "=f"(y) : "f"(x));
    return y;
}

// ---------------------------------------------------------------------------
// K1: att_h[b,j] = dot(h[b,:], W[j,:]) + bias[j]   (+ zero-init of d_out)
// grid (HH/8 = 64 j-groups, BB/4 = 16 b-groups) = 1024 blocks, block 256.
// No smem, no barrier: warp w owns j = bx*8+w; W row AND the 4 h rows are
// read directly from gmem (all L2-hot: W 2 MB, h 256 KB). The loop is a
// 2-stage software pipeline so each iteration's 5 independent LDG.128s
// (1 W + 4 h) are in flight while the previous iteration's FMAs retire —
// explicit MLP instead of the reg-starved serial chain ncu showed.
// First 256 blocks also zero d_out for k4's red.global accumulation.
// ---------------------------------------------------------------------------
__global__ void k1_att_h(const float* __restrict__ h,
                         const float* __restrict__ W,
                         const float* __restrict__ bias,
                         float* __restrict__ out) {
    const int warp = threadIdx.x >> 5;
    const int lane = threadIdx.x & 31;
    const int j    = blockIdx.x * 8 + warp;
    const int b0   = blockIdx.y * 4;

    // zero d_out: first 256 blocks (by = 0..3) cover exactly B*R floats
    if (blockIdx.y < 4)
        out[((size_t)blockIdx.y * 64 + blockIdx.x) * 256 + threadIdx.x] = 0.f;

    const float4* wr = (const float4*)(W + (size_t)j * RR);
    const float4* h0 = (const float4*)(h + (size_t)(b0 + 0) * RR);
    const float4* h1 = (const float4*)(h + (size_t)(b0 + 1) * RR);
    const float4* h2 = (const float4*)(h + (size_t)(b0 + 2) * RR);
    const float4* h3 = (const float4*)(h + (size_t)(b0 + 3) * RR);

    // stage 0 prefetch
    float4 w4 = wr[lane];
    float4 x0 = h0[lane], x1 = h1[lane], x2 = h2[lane], x3 = h3[lane];

    float a0 = 0.f, a1 = 0.f, a2 = 0.f, a3 = 0.f;
#pragma unroll
    for (int i = 0; i < RR / 128; i++) {          // 8 iterations
        float4 wn, y0, y1, y2, y3;
        if (i < RR / 128 - 1) {
            const int idx = (i + 1) * 32 + lane;
            wn = wr[idx];
            y0 = h0[idx]; y1 = h1[idx]; y2 = h2[idx]; y3 = h3[idx];
        }
        a0 += w4.x * x0.x + w4.y * x0.y + w4.z * x0.z + w4.w * x0.w;
        a1 += w4.x * x1.x + w4.y * x1.y + w4.z * x1.z + w4.w * x1.w;
        a2 += w4.x * x2.x + w4.y * x2.y + w4.z * x2.z + w4.w * x2.w;
        a3 += w4.x * x3.x + w4.y * x3.y + w4.z * x3.z + w4.w * x3.w;
        w4 = wn; x0 = y0; x1 = y1; x2 = y2; x3 = y3;
    }
#pragma unroll
    for (int o = 16; o; o >>= 1) {
        a0 += __shfl_down_sync(0xFFFFFFFFu, a0, o);
        a1 += __shfl_down_sync(0xFFFFFFFFu, a1, o);
        a2 += __shfl_down_sync(0xFFFFFFFFu, a2, o);
        a3 += __shfl_down_sync(0xFFFFFFFFu, a3, o);
    }
    if (lane == 0) {
        const float bj = bias[j];
        g_att_h[(b0 + 0) * HH + j] = a0 + bj;
        g_att_h[(b0 + 1) * HH + j] = a1 + bj;
        g_att_h[(b0 + 2) * HH + j] = a2 + bj;
        g_att_h[(b0 + 3) * HH + j] = a3 + bj;
    }
}

// ---------------------------------------------------------------------------
// K2: score[b,s] = sum_h tanh(p[b,s,h] + att_h[b,h]) * w_alpha[h]
// (b_alpha dropped: a constant shift cancels in softmax)
// grid (B, S/8), block 256 (8 warps, one s per warp). 256 MB streaming read.
// tanh via MUFU.TANH so the kernel stays HBM-bound.
// ---------------------------------------------------------------------------
__global__ void k2_scores(const float* __restrict__ p,
                          const float* __restrict__ w_alpha) {
    const int b = blockIdx.x;

    __shared__ float s_ah[HH];
    __shared__ float s_wa[HH];
    for (int i = threadIdx.x; i < HH / 4; i += blockDim.x) {
        ((float4*)s_ah)[i] = ((const float4*)(g_att_h + (size_t)b * HH))[i];
        ((float4*)s_wa)[i] = ((const float4*)w_alpha)[i];
    }
    __syncthreads();

    const int warp = threadIdx.x >> 5;
    const int lane = threadIdx.x & 31;
    const int s    = blockIdx.y * 8 + warp;

    const float4* pr = (const float4*)(p + ((size_t)b * SS + s) * HH);

    float acc = 0.f;
#pragma unroll
    for (int i = 0; i < HH / 128; i++) {           // 4 iterations
        float4 p4 = pr[i * 32 + lane];
        int k = (i * 32 + lane) * 4;
        acc += fast_tanh(p4.x + s_ah[k])     * s_wa[k];
        acc += fast_tanh(p4.y + s_ah[k + 1]) * s_wa[k + 1];
        acc += fast_tanh(p4.z + s_ah[k + 2]) * s_wa[k + 2];
        acc += fast_tanh(p4.w + s_ah[k + 3]) * s_wa[k + 3];
    }
#pragma unroll
    for (int o = 16; o; o >>= 1) acc += __shfl_down_sync(0xFFFFFFFFu, acc, o);
    if (lane == 0) g_score[b * SS + s] = acc;
}

// ---------------------------------------------------------------------------
// K4: fused softmax + partial weighted sums over an S-chunk (S-split), with
// direct red.global accumulation into d_out — no reduce kernel.
// grid (B, NSPLIT=16), block 256.
// Prologue: each block redundantly computes its batch row's masked softmax
// into smem (full 8 KB weight row).
// softmax -> *mask -> renorm  ==  e_i*m_i / sum_j(e_j*m_j)  (max-subtracted).
// Main loop: dense 4 KB-row streaming of att_feats (512 MB total).
// ---------------------------------------------------------------------------
__global__ void k4_wsum(const float* __restrict__ feats,
                        const int* __restrict__ mask,
                        float* __restrict__ out) {
    const int b   = blockIdx.x;
    const int sp  = blockIdx.y;
    const int s0  = sp * SCHUNK;
    const int tid = threadIdx.x;

    __shared__ float sw[SS];       // 8 KB: full weight row
    __shared__ float red[8];

    // --- load all SS scores for this batch row: thread tid owns tid + k*256
    float v[NOWN];
    int   m[NOWN];
#pragma unroll
    for (int k = 0; k < NOWN; k++) {
        v[k] = g_score[b * SS + k * 256 + tid];
        m[k] = mask[b * SS + k * 256 + tid];
    }

    // --- block max (over all scores, matching reference stability)
    float mx = v[0];
#pragma unroll
    for (int k = 1; k < NOWN; k++) mx = fmaxf(mx, v[k]);
#pragma unroll
    for (int o = 16; o; o >>= 1) mx = fmaxf(mx, __shfl_xor_sync(0xFFFFFFFFu, mx, o));
    if ((tid & 31) == 0) red[tid >> 5] = mx;
    __syncthreads();
    mx = fmaxf(fmaxf(fmaxf(red[0], red[1]), fmaxf(red[2], red[3])),
               fmaxf(fmaxf(red[4], red[5]), fmaxf(red[6], red[7])));
    __syncthreads();

    // --- masked exponentials + block sum
    float e[NOWN];
    float sum = 0.f;
#pragma unroll
    for (int k = 0; k < NOWN; k++) {
        e[k] = m[k] ? __expf(v[k] - mx) : 0.f;
        sum += e[k];
    }
#pragma unroll
    for (int o = 16; o; o >>= 1) sum += __shfl_xor_sync(0xFFFFFFFFu, sum, o);
    if ((tid & 31) == 0) red[tid >> 5] = sum;
    __syncthreads();
    sum = red[0] + red[1] + red[2] + red[3] + red[4] + red[5] + red[6] + red[7];
    const float inv = 1.f / sum;

#pragma unroll
    for (int k = 0; k < NOWN; k++) sw[k * 256 + tid] = e[k] * inv;
    __syncthreads();

    // --- streaming weighted sum over this block's 128-row chunk
    const float4* base = (const float4*)(feats + ((size_t)b * SS + s0) * RR) + tid;
    const float*  wrow = sw + s0;

    float4 acc = make_float4(0.f, 0.f, 0.f, 0.f);
#pragma unroll 4
    for (int i = 0; i < SCHUNK; i++) {
        float4 f = base[(size_t)i * (RR / 4)];
        float w = wrow[i];
        acc.x += w * f.x; acc.y += w * f.y; acc.z += w * f.z; acc.w += w * f.w;
    }

    // --- accumulate directly into the output (REDG; 16 contributors/address)
    float* o = out + (size_t)b * RR + tid * 4;
    atomicAdd(o + 0, acc.x);
    atomicAdd(o + 1, acc.y);
    atomicAdd(o + 2, acc.z);
    atomicAdd(o + 3, acc.w);
}

// ---------------------------------------------------------------------------
extern "C" void kernel_launch(void* const* d_in, const int* in_sizes, int n_in,
                              void* d_out, int out_size) {
    const float* h         = (const float*)d_in[0];
    const float* att_feats = (const float*)d_in[1];
    const float* p_att     = (const float*)d_in[2];
    const int*   masks     = (const int*)  d_in[3];
    const float* W         = (const float*)d_in[4];
    const float* b_h2att   = (const float*)d_in[5];
    const float* w_alpha   = (const float*)d_in[6];
    // d_in[7] = b_alpha: unused (constant shift cancels in softmax)
    float*       out       = (float*)d_out;

    k1_att_h  <<<dim3(HH / 8, BB / 4), 256>>>(h, W, b_h2att, out);
    k2_scores <<<dim3(BB, SS / 8),     256>>>(p_att, w_alpha);
    k4_wsum   <<<dim3(BB, NSPLIT),     256>>>(att_feats, masks, out);
}

// round 13
// speedup vs baseline: 1.0307x; 1.0307x over previous
#include <cuda_runtime.h>
#include <cuda_bf16.h>

#define BB 64
#define SS 2048
#define RR 1024
#define HH 512
#define NOWN 8                  // scores owned per thread in softmax prologue
#define NSPLIT 16               // S-chunks in k4 (1024 blocks -> 6.9 waves)
#define SCHUNK (SS / NSPLIT)    // 128
#define BPB 8                   // batches per k1 block

// Scratch (allocation-free rule: __device__ globals)
__device__ float g_att_h[BB * HH];   // 128 KB
__device__ float g_score[BB * SS];   // 512 KB (raw scores; softmax fused into k4)

__device__ __forceinline__ float fast_tanh(float x) {
    float y;
    asm("tanh.approx.f32 %0, %1;" : "=f"(y) : "f"(x));
    return y;
}

// ---------------------------------------------------------------------------
// K1: att_h[b,j] = dot(h[b,:], W[j,:]) + bias[j]   (+ zero-init of d_out)
// grid (HH/8 = 64 j-groups, BB/8 = 8 b-groups) = 512 blocks, block 256.
// R11 structure (proven fastest: direct LDG.128 of the L2-hot W row, h rows
// staged in smem) with batch-per-block doubled 4 -> 8: halves redundant W L2
// traffic (32 MB -> 16 MB) and doubles arithmetic intensity per W load.
// Each warp owns j = bx*8+w; 8 independent accumulators give ILP 8.
// First 256 blocks (by < 4) zero d_out for k4's red.global accumulation.
// ---------------------------------------------------------------------------
__global__ void k1_att_h(const float* __restrict__ h,
                         const float* __restrict__ W,
                         const float* __restrict__ bias,
                         float* __restrict__ out) {
    const int warp = threadIdx.x >> 5;
    const int lane = threadIdx.x & 31;
    const int j    = blockIdx.x * 8 + warp;
    const int b0   = blockIdx.y * BPB;

    // zero d_out: blocks with by = 0..3 cover exactly B*R = 65536 floats
    if (blockIdx.y < 4)
        out[((size_t)blockIdx.y * 64 + blockIdx.x) * 256 + threadIdx.x] = 0.f;

    __shared__ float sh[BPB * RR];    // 32 KB: this block's 8 h rows

    const float4* Hg = (const float4*)(h + (size_t)b0 * RR);
#pragma unroll
    for (int k = 0; k < BPB; k++)
        ((float4*)sh)[threadIdx.x + k * 256] = Hg[threadIdx.x + k * 256];

    __syncthreads();

    const float4* wr = (const float4*)(W + (size_t)j * RR);

    float a[BPB];
#pragma unroll
    for (int k = 0; k < BPB; k++) a[k] = 0.f;

#pragma unroll
    for (int i = 0; i < RR / 128; i++) {          // 8 iterations
        const int idx = i * 32 + lane;
        float4 w4 = wr[idx];                       // LDG.128, L2-hot
#pragma unroll
        for (int k = 0; k < BPB; k++) {
            float4 x = ((const float4*)(sh + k * RR))[idx];
            a[k] += w4.x * x.x + w4.y * x.y + w4.z * x.z + w4.w * x.w;
        }
    }
#pragma unroll
    for (int o = 16; o; o >>= 1) {
#pragma unroll
        for (int k = 0; k < BPB; k++)
            a[k] += __shfl_down_sync(0xFFFFFFFFu, a[k], o);
    }
    if (lane == 0) {
        const float bj = bias[j];
#pragma unroll
        for (int k = 0; k < BPB; k++)
            g_att_h[(b0 + k) * HH + j] = a[k] + bj;
    }
}

// ---------------------------------------------------------------------------
// K2: score[b,s] = sum_h tanh(p[b,s,h] + att_h[b,h]) * w_alpha[h]
// (b_alpha dropped: a constant shift cancels in softmax)
// grid (B, S/8), block 256 (8 warps, one s per warp). 256 MB streaming read.
// tanh via MUFU.TANH so the kernel stays HBM-bound.
// ---------------------------------------------------------------------------
__global__ void k2_scores(const float* __restrict__ p,
                          const float* __restrict__ w_alpha) {
    const int b = blockIdx.x;

    __shared__ float s_ah[HH];
    __shared__ float s_wa[HH];
    for (int i = threadIdx.x; i < HH / 4; i += blockDim.x) {
        ((float4*)s_ah)[i] = ((const float4*)(g_att_h + (size_t)b * HH))[i];
        ((float4*)s_wa)[i] = ((const float4*)w_alpha)[i];
    }
    __syncthreads();

    const int warp = threadIdx.x >> 5;
    const int lane = threadIdx.x & 31;
    const int s    = blockIdx.y * 8 + warp;

    const float4* pr = (const float4*)(p + ((size_t)b * SS + s) * HH);

    float acc = 0.f;
#pragma unroll
    for (int i = 0; i < HH / 128; i++) {           // 4 iterations
        float4 p4 = pr[i * 32 + lane];
        int k = (i * 32 + lane) * 4;
        acc += fast_tanh(p4.x + s_ah[k])     * s_wa[k];
        acc += fast_tanh(p4.y + s_ah[k + 1]) * s_wa[k + 1];
        acc += fast_tanh(p4.z + s_ah[k + 2]) * s_wa[k + 2];
        acc += fast_tanh(p4.w + s_ah[k + 3]) * s_wa[k + 3];
    }
#pragma unroll
    for (int o = 16; o; o >>= 1) acc += __shfl_down_sync(0xFFFFFFFFu, acc, o);
    if (lane == 0) g_score[b * SS + s] = acc;
}

// ---------------------------------------------------------------------------
// K4: fused softmax + partial weighted sums over an S-chunk (S-split), with
// direct red.global accumulation into d_out — no reduce kernel.
// grid (B, NSPLIT=16), block 256.
// Prologue: each block redundantly computes its batch row's masked softmax
// into smem (full 8 KB weight row).
// softmax -> *mask -> renorm  ==  e_i*m_i / sum_j(e_j*m_j)  (max-subtracted).
// Main loop: dense 4 KB-row streaming of att_feats (512 MB total).
// ---------------------------------------------------------------------------
__global__ void k4_wsum(const float* __restrict__ feats,
                        const int* __restrict__ mask,
                        float* __restrict__ out) {
    const int b   = blockIdx.x;
    const int sp  = blockIdx.y;
    const int s0  = sp * SCHUNK;
    const int tid = threadIdx.x;

    __shared__ float sw[SS];       // 8 KB: full weight row
    __shared__ float red[8];

    // --- load all SS scores for this batch row: thread tid owns tid + k*256
    float v[NOWN];
    int   m[NOWN];
#pragma unroll
    for (int k = 0; k < NOWN; k++) {
        v[k] = g_score[b * SS + k * 256 + tid];
        m[k] = mask[b * SS + k * 256 + tid];
    }

    // --- block max (over all scores, matching reference stability)
    float mx = v[0];
#pragma unroll
    for (int k = 1; k < NOWN; k++) mx = fmaxf(mx, v[k]);
#pragma unroll
    for (int o = 16; o; o >>= 1) mx = fmaxf(mx, __shfl_xor_sync(0xFFFFFFFFu, mx, o));
    if ((tid & 31) == 0) red[tid >> 5] = mx;
    __syncthreads();
    mx = fmaxf(fmaxf(fmaxf(red[0], red[1]), fmaxf(red[2], red[3])),
               fmaxf(fmaxf(red[4], red[5]), fmaxf(red[6], red[7])));
    __syncthreads();

    // --- masked exponentials + block sum
    float e[NOWN];
    float sum = 0.f;
#pragma unroll
    for (int k = 0; k < NOWN; k++) {
        e[k] = m[k] ? __expf(v[k] - mx) : 0.f;
        sum += e[k];
    }
#pragma unroll
    for (int o = 16; o; o >>= 1) sum += __shfl_xor_sync(0xFFFFFFFFu, sum, o);
    if ((tid & 31) == 0) red[tid >> 5] = sum;
    __syncthreads();
    sum = red[0] + red[1] + red[2] + red[3] + red[4] + red[5] + red[6] + red[7];
    const float inv = 1.f / sum;

#pragma unroll
    for (int k = 0; k < NOWN; k++) sw[k * 256 + tid] = e[k] * inv;
    __syncthreads();

    // --- streaming weighted sum over this block's 128-row chunk
    const float4* base = (const float4*)(feats + ((size_t)b * SS + s0) * RR) + tid;
    const float*  wrow = sw + s0;

    float4 acc = make_float4(0.f, 0.f, 0.f, 0.f);
#pragma unroll 4
    for (int i = 0; i < SCHUNK; i++) {
        float4 f = base[(size_t)i * (RR / 4)];
        float w = wrow[i];
        acc.x += w * f.x; acc.y += w * f.y; acc.z += w * f.z; acc.w += w * f.w;
    }

    // --- accumulate directly into the output (REDG; 16 contributors/address)
    float* o = out + (size_t)b * RR + tid * 4;
    atomicAdd(o + 0, acc.x);
    atomicAdd(o + 1, acc.y);
    atomicAdd(o + 2, acc.z);
    atomicAdd(o + 3, acc.w);
}

// ---------------------------------------------------------------------------
extern "C" void kernel_launch(void* const* d_in, const int* in_sizes, int n_in,
                              void* d_out, int out_size) {
    const float* h         = (const float*)d_in[0];
    const float* att_feats = (const float*)d_in[1];
    const float* p_att     = (const float*)d_in[2];
    const int*   masks     = (const int*)  d_in[3];
    const float* W         = (const float*)d_in[4];
    const float* b_h2att   = (const float*)d_in[5];
    const float* w_alpha   = (const float*)d_in[6];
    // d_in[7] = b_alpha: unused (constant shift cancels in softmax)
    float*       out       = (float*)d_out;

    k1_att_h  <<<dim3(HH / 8, BB / BPB), 256>>>(h, W, b_h2att, out);
    k2_scores <<<dim3(BB, SS / 8),       256>>>(p_att, w_alpha);
    k4_wsum   <<<dim3(BB, NSPLIT),       256>>>(att_feats, masks, out);
}